// round 1
// baseline (speedup 1.0000x reference)
#include <cuda_runtime.h>

#define BB 4
#define LL 1024
#define DD 768
#define HH 12
#define DHH 64

// Scratch (static device globals — allocation-free per harness rules)
__device__ float g_M[(size_t)HH * DD * DD];          // 28.3 MB : q_n^T k_n
__device__ float g_A[(size_t)BB * HH * LL * DD];     // 151 MB  : X_b M_n
__device__ float g_S[(size_t)BB * HH * LL * LL];     // 201 MB  : scores / softmax
__device__ float g_V[(size_t)BB * HH * LL * DHH];    // 12.6 MB : X_b v_n^T

// ---------------------------------------------------------------------------
// Generic batched tiled GEMM.
//  C[m,n] = sum_k opA(A)[m,k] * opB(B)[k,n]
//  !TA: A stored [M, lda] row-major (element A[m*lda+k])
//   TA: A stored [K, lda]            (element A[k*lda+m])
//  !TB: B stored [K, ldb]            (element B[k*ldb+n])
//   TB: B stored [N, ldb]            (element B[n*ldb+k])
//  Per-batch offsets: off = (z/HH)*s1 + (z%HH)*s2
// ---------------------------------------------------------------------------
template<bool TA, bool TB>
__global__ void gemm_kernel(const float* __restrict__ Ag,
                            const float* __restrict__ Bg,
                            float* __restrict__ Cg,
                            int M, int N, int K,
                            int lda, int ldb, int ldc,
                            long as1, long as2,
                            long bs1, long bs2,
                            long cs1, long cs2)
{
    constexpr int BM = 64, BN = 64, BK = 16;
    __shared__ float As[BK][BM + 4];
    __shared__ float Bs[BK][BN + 4];

    const int z = blockIdx.z;
    const float* A = Ag + (long)(z / HH) * as1 + (long)(z % HH) * as2;
    const float* Bp = Bg + (long)(z / HH) * bs1 + (long)(z % HH) * bs2;
    float* C = Cg + (long)(z / HH) * cs1 + (long)(z % HH) * cs2;

    const int m0 = blockIdx.y * BM;
    const int n0 = blockIdx.x * BN;
    const int tid = threadIdx.x;           // 256 threads
    const int tx = tid & 15, ty = tid >> 4;

    float acc[4][4] = {};

    for (int kt = 0; kt < K; kt += BK) {
        #pragma unroll
        for (int i = 0; i < 4; i++) {
            const int idx = tid + i * 256;   // 1024 elements per tile
            // ---- A tile -> As[k][m]
            {
                int m, k;
                if (!TA) { m = idx / BK; k = idx % BK; }
                else     { k = idx / BM; m = idx % BM; }
                const int gm = m0 + m, gk = kt + k;
                float v = 0.f;
                if (gm < M) v = TA ? A[(long)gk * lda + gm]
                                   : A[(long)gm * lda + gk];
                As[k][m] = v;
            }
            // ---- B tile -> Bs[k][n]
            {
                int n, k;
                if (!TB) { k = idx / BN; n = idx % BN; }
                else     { n = idx / BK; k = idx % BK; }
                const int gn = n0 + n, gk = kt + k;
                float v = 0.f;
                if (gn < N) v = TB ? Bp[(long)gn * ldb + gk]
                                   : Bp[(long)gk * ldb + gn];
                Bs[k][n] = v;
            }
        }
        __syncthreads();

        #pragma unroll
        for (int kk = 0; kk < BK; kk++) {
            const float4 a4 = *(const float4*)&As[kk][ty * 4];
            const float4 b4 = *(const float4*)&Bs[kk][tx * 4];
            const float a[4] = {a4.x, a4.y, a4.z, a4.w};
            const float b[4] = {b4.x, b4.y, b4.z, b4.w};
            #pragma unroll
            for (int i = 0; i < 4; i++)
                #pragma unroll
                for (int j = 0; j < 4; j++)
                    acc[i][j] += a[i] * b[j];
        }
        __syncthreads();
    }

    #pragma unroll
    for (int i = 0; i < 4; i++) {
        const int gm = m0 + ty * 4 + i;
        if (gm >= M) continue;
        #pragma unroll
        for (int j = 0; j < 4; j++) {
            const int gn = n0 + tx * 4 + j;
            if (gn < N) C[(long)gm * ldc + gn] = acc[i][j];
        }
    }
}

// ---------------------------------------------------------------------------
// Row softmax (in place). One 256-thread block per row of length `cols`.
// ---------------------------------------------------------------------------
__global__ void softmax_kernel(float* __restrict__ S, int cols)
{
    float* p = S + (long)blockIdx.x * cols;
    const int tid = threadIdx.x;
    __shared__ float red[8];

    // max
    float vmax = -1e30f;
    for (int i = tid; i < cols; i += 256) vmax = fmaxf(vmax, p[i]);
    #pragma unroll
    for (int o = 16; o > 0; o >>= 1) vmax = fmaxf(vmax, __shfl_xor_sync(~0u, vmax, o));
    if ((tid & 31) == 0) red[tid >> 5] = vmax;
    __syncthreads();
    if (tid < 32) {
        float v = (tid < 8) ? red[tid] : -1e30f;
        #pragma unroll
        for (int o = 4; o > 0; o >>= 1) v = fmaxf(v, __shfl_xor_sync(~0u, v, o));
        if (tid == 0) red[0] = v;
    }
    __syncthreads();
    vmax = red[0];
    __syncthreads();

    // exp + sum
    float s = 0.f;
    for (int i = tid; i < cols; i += 256) {
        const float e = __expf(p[i] - vmax);
        p[i] = e;
        s += e;
    }
    #pragma unroll
    for (int o = 16; o > 0; o >>= 1) s += __shfl_xor_sync(~0u, s, o);
    if ((tid & 31) == 0) red[tid >> 5] = s;
    __syncthreads();
    if (tid < 32) {
        float v = (tid < 8) ? red[tid] : 0.f;
        #pragma unroll
        for (int o = 4; o > 0; o >>= 1) v += __shfl_xor_sync(~0u, v, o);
        if (tid == 0) red[0] = v;
    }
    __syncthreads();
    const float inv = 1.0f / red[0];
    for (int i = tid; i < cols; i += 256) p[i] *= inv;
}

// ---------------------------------------------------------------------------
extern "C" void kernel_launch(void* const* d_in, const int* in_sizes, int n_in,
                              void* d_out, int out_size)
{
    const float* x = (const float*)d_in[0];   // [B, L, D]
    const float* k = (const float*)d_in[1];   // [H, D, D]
    const float* q = (const float*)d_in[2];   // [H, D, D]
    const float* v = (const float*)d_in[3];   // [H, DH, D]
    float* out = (float*)d_out;               // [B, L, D]

    float *pM, *pA, *pS, *pV;
    cudaGetSymbolAddress((void**)&pM, g_M);
    cudaGetSymbolAddress((void**)&pA, g_A);
    cudaGetSymbolAddress((void**)&pS, g_S);
    cudaGetSymbolAddress((void**)&pV, g_V);

    const long LD = (long)LL * DD;            // 786432
    const long L2 = (long)LL * LL;            // 1048576
    const long DSQ = (long)DD * DD;           // 589824
    const long LDH = (long)LL * DHH;          // 65536

    dim3 blk(256);

    // 1) M_n = q_n^T * k_n   : C[d,e] = sum_c q[n,c,d]*k[n,c,e]   (TA, !TB), batch 12
    gemm_kernel<true, false><<<dim3(DD/64, DD/64, HH), blk>>>(
        q, k, pM, DD, DD, DD, DD, DD, DD,
        0, DSQ,   0, DSQ,   0, DSQ);

    // 2) A_bn = X_b * M_n    : [L,D]x[D,D]                         (!TA,!TB), batch 48
    gemm_kernel<false, false><<<dim3(DD/64, LL/64, BB*HH), blk>>>(
        x, pM, pA, LL, DD, DD, DD, DD, DD,
        LD, 0,    0, DSQ,   HH*LD, LD);

    // 3) S = A_bn * X_b^T    : [L,D]x[D,L]                         (!TA, TB), batch 48
    gemm_kernel<false, true><<<dim3(LL/64, LL/64, BB*HH), blk>>>(
        pA, x, pS, LL, LL, DD, DD, DD, LL,
        HH*LD, LD,   LD, 0,   HH*L2, L2);

    // 4) softmax over last dim of S (48*1024 rows of 1024)
    softmax_kernel<<<dim3(BB*HH*LL), blk>>>(pS, LL);

    // 5) Vt[b,n][m,d] = X_b * v_n^T : [L,D]x[D,DH]                 (!TA, TB), batch 48
    gemm_kernel<false, true><<<dim3(DHH/64, LL/64, BB*HH), blk>>>(
        x, v, pV, LL, DHH, DD, DD, DD, DHH,
        LD, 0,    0, (long)DHH*DD,   HH*LDH, LDH);

    // 6) out[b, l, n*64+d] = S[b,n] * Vt[b,n] : [L,L]x[L,DH]       (!TA,!TB), batch 48
    gemm_kernel<false, false><<<dim3(DHH/64, LL/64, BB*HH), blk>>>(
        pS, pV, out, LL, DHH, LL, LL, DHH, DD,
        HH*L2, L2,   HH*LDH, LDH,   LD, DHH);
}

// round 2
// speedup vs baseline: 2.7331x; 2.7331x over previous
#include <cuda_runtime.h>

#define BB 4
#define LL 1024
#define DD 768
#define HH 12
#define DHH 64

// Scratch (static device globals — allocation-free per harness rules)
__device__ float g_M[(size_t)HH * DD * DD];          // 28.3 MB : q_n^T k_n
__device__ float g_A[(size_t)BB * HH * LL * DD];     // 151 MB  : X_b M_n
__device__ float g_S[(size_t)BB * HH * LL * LL];     // 201 MB  : scores / softmax
__device__ float g_V[(size_t)BB * HH * LL * DHH];    // 12.6 MB : X_b v_n^T

__device__ __forceinline__ unsigned f2tf(float x) {
    unsigned u;
    asm("cvt.rna.tf32.f32 %0, %1;" : "=r"(u) : "f"(x));
    return u;
}

__device__ __forceinline__ void mma_tf32(float* c, const unsigned* a, const unsigned* b) {
    asm volatile(
        "mma.sync.aligned.m16n8k8.row.col.f32.tf32.tf32.f32 "
        "{%0,%1,%2,%3}, {%4,%5,%6,%7}, {%8,%9}, {%0,%1,%2,%3};"
        : "+f"(c[0]), "+f"(c[1]), "+f"(c[2]), "+f"(c[3])
        : "r"(a[0]), "r"(a[1]), "r"(a[2]), "r"(a[3]), "r"(b[0]), "r"(b[1]));
}

// Swizzle: physical col = logical col ^ (((row>>2)&7)<<2). Conflict-free for
// both transposed tile stores and the m16n8k8 fragment load pattern.
#define SWC(row) ((((row) >> 2) & 7) << 2)

// ---------------------------------------------------------------------------
// Batched tf32 tensor-core GEMM.  C[m,n] = sum_k opA(A)[m,k] * opB(B)[k,n]
//  !TA: A[m*lda+k]   TA: A[k*lda+m]   !TB: B[k*ldb+n]   TB: B[n*ldb+k]
// Block 128x128x32, 4 warps of 64x64. M,K must be multiples of 128/32 (true
// for all call sites); N may be ragged (guarded).
// ---------------------------------------------------------------------------
template<bool TA, bool TB>
__global__ __launch_bounds__(128)
void gemm_tc(const float* __restrict__ Ag, const float* __restrict__ Bg,
             float* __restrict__ Cg, int M, int N, int K,
             int lda, int ldb, int ldc,
             long as1, long as2, long bs1, long bs2, long cs1, long cs2)
{
    constexpr int BM = 128, BN = 128, BK = 32;
    __shared__ unsigned As[BK][136];
    __shared__ unsigned Bs[BK][136];

    const int z = blockIdx.z;
    const float* A = Ag + (long)(z / HH) * as1 + (long)(z % HH) * as2;
    const float* B = Bg + (long)(z / HH) * bs1 + (long)(z % HH) * bs2;
    float* C = Cg + (long)(z / HH) * cs1 + (long)(z % HH) * cs2;

    const int m0 = blockIdx.y * BM;
    const int n0 = blockIdx.x * BN;
    const int tid = threadIdx.x;
    const int lane = tid & 31;
    const int wid = tid >> 5;          // 0..3
    const int wm = (wid & 1) * 64;
    const int wn = (wid >> 1) * 64;
    const int lm = lane >> 2;          // 0..7
    const int lk = lane & 3;           // 0..3

    float acc[4][8][4];
    #pragma unroll
    for (int i = 0; i < 4; i++)
        #pragma unroll
        for (int j = 0; j < 8; j++)
            #pragma unroll
            for (int r = 0; r < 4; r++) acc[i][j][r] = 0.f;

    for (int kt = 0; kt < K; kt += BK) {
        // ---- A tile -> As[k][m^sw] (tf32-rounded) ----
        if (!TA) {
            #pragma unroll
            for (int i = 0; i < 8; i++) {
                const int g = tid + i * 128;
                const int m = g >> 3;
                const int kq = (g & 7) << 2;
                const float4 v = *(const float4*)&A[(long)(m0 + m) * lda + kt + kq];
                const int c = SWC(kq);         // rows kq..kq+3 share (row>>2)
                As[kq + 0][m ^ c] = f2tf(v.x);
                As[kq + 1][m ^ c] = f2tf(v.y);
                As[kq + 2][m ^ c] = f2tf(v.z);
                As[kq + 3][m ^ c] = f2tf(v.w);
            }
        } else {
            #pragma unroll
            for (int i = 0; i < 8; i++) {
                const int g = tid + i * 128;
                const int kq = g >> 5;
                const int m4 = (g & 31) << 2;
                const float4 v = *(const float4*)&A[(long)(kt + kq) * lda + m0 + m4];
                const int c = SWC(kq);
                unsigned* p = &As[kq][m4 ^ c];  // contiguous: c has no bits <2
                p[0] = f2tf(v.x); p[1] = f2tf(v.y); p[2] = f2tf(v.z); p[3] = f2tf(v.w);
            }
        }
        // ---- B tile -> Bs[k][n^sw] ----
        if (!TB) {
            #pragma unroll
            for (int i = 0; i < 8; i++) {
                const int g = tid + i * 128;
                const int kq = g >> 5;
                const int n4 = (g & 31) << 2;
                float4 v = make_float4(0.f, 0.f, 0.f, 0.f);
                if (n0 + n4 < N) v = *(const float4*)&B[(long)(kt + kq) * ldb + n0 + n4];
                const int c = SWC(kq);
                unsigned* p = &Bs[kq][n4 ^ c];
                p[0] = f2tf(v.x); p[1] = f2tf(v.y); p[2] = f2tf(v.z); p[3] = f2tf(v.w);
            }
        } else {
            #pragma unroll
            for (int i = 0; i < 8; i++) {
                const int g = tid + i * 128;
                const int n = g >> 3;
                const int kq = (g & 7) << 2;
                float4 v = make_float4(0.f, 0.f, 0.f, 0.f);
                if (n0 + n < N) v = *(const float4*)&B[(long)(n0 + n) * ldb + kt + kq];
                const int c = SWC(kq);
                Bs[kq + 0][n ^ c] = f2tf(v.x);
                Bs[kq + 1][n ^ c] = f2tf(v.y);
                Bs[kq + 2][n ^ c] = f2tf(v.z);
                Bs[kq + 3][n ^ c] = f2tf(v.w);
            }
        }
        __syncthreads();

        #pragma unroll
        for (int ks = 0; ks < 4; ks++) {
            const int k0 = ks * 8;
            const int r1 = k0 + lk;
            const int r2 = k0 + lk + 4;
            const int c1 = SWC(r1);
            const int c2 = SWC(r2);
            unsigned a[4][4], b[8][2];
            #pragma unroll
            for (int mt = 0; mt < 4; mt++) {
                const int mr = wm + mt * 16 + lm;
                a[mt][0] = As[r1][mr ^ c1];
                a[mt][1] = As[r1][(mr + 8) ^ c1];
                a[mt][2] = As[r2][mr ^ c2];
                a[mt][3] = As[r2][(mr + 8) ^ c2];
            }
            #pragma unroll
            for (int nt = 0; nt < 8; nt++) {
                const int nc = wn + nt * 8 + lm;
                b[nt][0] = Bs[r1][nc ^ c1];
                b[nt][1] = Bs[r2][nc ^ c2];
            }
            #pragma unroll
            for (int mt = 0; mt < 4; mt++)
                #pragma unroll
                for (int nt = 0; nt < 8; nt++)
                    mma_tf32(acc[mt][nt], a[mt], b[nt]);
        }
        __syncthreads();
    }

    // ---- epilogue ----
    #pragma unroll
    for (int mt = 0; mt < 4; mt++) {
        const int r0 = m0 + wm + mt * 16 + lm;
        #pragma unroll
        for (int nt = 0; nt < 8; nt++) {
            const int c0 = n0 + wn + nt * 8 + 2 * lk;
            if (c0 < N) {
                C[(long)r0 * ldc + c0]           = acc[mt][nt][0];
                C[(long)r0 * ldc + c0 + 1]       = acc[mt][nt][1];
                C[(long)(r0 + 8) * ldc + c0]     = acc[mt][nt][2];
                C[(long)(r0 + 8) * ldc + c0 + 1] = acc[mt][nt][3];
            }
        }
    }
}

// ---------------------------------------------------------------------------
// Row softmax (in place). One 256-thread block per row of length `cols`.
// ---------------------------------------------------------------------------
__global__ void softmax_kernel(float* __restrict__ S, int cols)
{
    float* p = S + (long)blockIdx.x * cols;
    const int tid = threadIdx.x;
    __shared__ float red[8];

    float vmax = -1e30f;
    for (int i = tid; i < cols; i += 256) vmax = fmaxf(vmax, p[i]);
    #pragma unroll
    for (int o = 16; o > 0; o >>= 1) vmax = fmaxf(vmax, __shfl_xor_sync(~0u, vmax, o));
    if ((tid & 31) == 0) red[tid >> 5] = vmax;
    __syncthreads();
    if (tid < 32) {
        float v = (tid < 8) ? red[tid] : -1e30f;
        #pragma unroll
        for (int o = 4; o > 0; o >>= 1) v = fmaxf(v, __shfl_xor_sync(~0u, v, o));
        if (tid == 0) red[0] = v;
    }
    __syncthreads();
    vmax = red[0];
    __syncthreads();

    float s = 0.f;
    for (int i = tid; i < cols; i += 256) {
        const float e = __expf(p[i] - vmax);
        p[i] = e;
        s += e;
    }
    #pragma unroll
    for (int o = 16; o > 0; o >>= 1) s += __shfl_xor_sync(~0u, s, o);
    if ((tid & 31) == 0) red[tid >> 5] = s;
    __syncthreads();
    if (tid < 32) {
        float v = (tid < 8) ? red[tid] : 0.f;
        #pragma unroll
        for (int o = 4; o > 0; o >>= 1) v += __shfl_xor_sync(~0u, v, o);
        if (tid == 0) red[0] = v;
    }
    __syncthreads();
    const float inv = 1.0f / red[0];
    for (int i = tid; i < cols; i += 256) p[i] *= inv;
}

// ---------------------------------------------------------------------------
extern "C" void kernel_launch(void* const* d_in, const int* in_sizes, int n_in,
                              void* d_out, int out_size)
{
    const float* x = (const float*)d_in[0];   // [B, L, D]
    const float* k = (const float*)d_in[1];   // [H, D, D]
    const float* q = (const float*)d_in[2];   // [H, D, D]
    const float* v = (const float*)d_in[3];   // [H, DH, D]
    float* out = (float*)d_out;               // [B, L, D]

    float *pM, *pA, *pS, *pV;
    cudaGetSymbolAddress((void**)&pM, g_M);
    cudaGetSymbolAddress((void**)&pA, g_A);
    cudaGetSymbolAddress((void**)&pS, g_S);
    cudaGetSymbolAddress((void**)&pV, g_V);

    const long LD  = (long)LL * DD;
    const long L2  = (long)LL * LL;
    const long DSQ = (long)DD * DD;
    const long LDH = (long)LL * DHH;

    dim3 blk(128);

    // 1) M_n = q_n^T * k_n : [D,D,D], batch 12          (TA, !TB)
    gemm_tc<true, false><<<dim3(DD/128, DD/128, HH), blk>>>(
        q, k, pM, DD, DD, DD, DD, DD, DD,
        0, DSQ,   0, DSQ,   0, DSQ);

    // 2) A_bn = X_b * M_n : [L,D]x[D,D], batch 48       (!TA,!TB)
    gemm_tc<false, false><<<dim3(DD/128, LL/128, BB*HH), blk>>>(
        x, pM, pA, LL, DD, DD, DD, DD, DD,
        LD, 0,    0, DSQ,   HH*LD, LD);

    // 3) S = A_bn * X_b^T : [L,D]x[D,L], batch 48       (!TA, TB)
    gemm_tc<false, true><<<dim3(LL/128, LL/128, BB*HH), blk>>>(
        pA, x, pS, LL, LL, DD, DD, DD, LL,
        HH*LD, LD,   LD, 0,   HH*L2, L2);

    // 4) softmax over last dim of S
    softmax_kernel<<<dim3(BB*HH*LL), dim3(256)>>>(pS, LL);

    // 5) Vt = X_b * v_n^T : [L,D]x[D,DH], batch 48      (!TA, TB)
    gemm_tc<false, true><<<dim3(1, LL/128, BB*HH), blk>>>(
        x, v, pV, LL, DHH, DD, DD, DD, DHH,
        LD, 0,    0, (long)DHH*DD,   HH*LDH, LDH);

    // 6) out = S * Vt : [L,L]x[L,DH], batch 48          (!TA,!TB)
    gemm_tc<false, false><<<dim3(1, LL/128, BB*HH), blk>>>(
        pS, pV, out, LL, DHH, LL, LL, DHH, DD,
        HH*L2, L2,   HH*LDH, LDH,   LD, DHH);
}

// round 3
// speedup vs baseline: 3.1638x; 1.1576x over previous
#include <cuda_runtime.h>

#define BB 4
#define LL 1024
#define DD 768
#define HH 12
#define DHH 64

// Scratch (static device globals — allocation-free per harness rules)
__device__ float g_M[(size_t)HH * DD * DD];          // q_n^T k_n
__device__ float g_A[(size_t)BB * HH * LL * DD];     // X_b M_n
__device__ float g_S[(size_t)BB * HH * LL * LL];     // scores / softmax
__device__ float g_V[(size_t)BB * HH * LL * DHH];    // X_b v_n^T
// tf32-prerounded copies of the inputs (cp.async copies raw bytes, so
// rounding must happen before the GEMM reads them)
__device__ float g_x[(size_t)BB * LL * DD];
__device__ float g_k[(size_t)HH * DD * DD];
__device__ float g_q[(size_t)HH * DD * DD];
__device__ float g_v[(size_t)HH * DHH * DD];

__device__ __forceinline__ unsigned f2tf(float x) {
    unsigned u;
    asm("cvt.rna.tf32.f32 %0, %1;" : "=r"(u) : "f"(x));
    return u;
}
__device__ __forceinline__ float rtf(float x) { return __uint_as_float(f2tf(x)); }

__device__ __forceinline__ void mma_tf32(float* c, const unsigned* a, const unsigned* b) {
    asm volatile(
        "mma.sync.aligned.m16n8k8.row.col.f32.tf32.tf32.f32 "
        "{%0,%1,%2,%3}, {%4,%5,%6,%7}, {%8,%9}, {%0,%1,%2,%3};"
        : "+f"(c[0]), "+f"(c[1]), "+f"(c[2]), "+f"(c[3])
        : "r"(a[0]), "r"(a[1]), "r"(a[2]), "r"(a[3]), "r"(b[0]), "r"(b[1]));
}

#define SWC(row) ((((row) >> 2) & 7) << 2)

__device__ __forceinline__ unsigned sa(const void* p) {
    return (unsigned)__cvta_generic_to_shared(p);
}
__device__ __forceinline__ void cpa16(unsigned saddr, const void* g, bool pred) {
    int sz = pred ? 16 : 0;
    asm volatile("cp.async.cg.shared.global [%0], [%1], 16, %2;\n"
                 :: "r"(saddr), "l"(g), "r"(sz));
}
__device__ __forceinline__ void cp_commit() {
    asm volatile("cp.async.commit_group;\n" ::: "memory");
}
__device__ __forceinline__ void cp_wait1() {
    asm volatile("cp.async.wait_group 1;\n" ::: "memory");
}

// ---------------------------------------------------------------------------
// Batched tf32 tensor-core GEMM, cp.async double-buffered.
//  C[m,n] = sum_k opA(A)[m,k] * opB(B)[k,n]
//  !TA: A[m*lda+k]   TA: A[k*lda+m]   !TB: B[k*ldb+n]   TB: B[n*ldb+k]
// Block 128x128x16(x2 stages), 8 warps (2M x 4N) of 64x32.
// M, K multiples of 128/16 (true at all call sites); N may be < BN (guarded).
// RND: round output to tf32 (for intermediates consumed by later GEMMs).
// smem layouts:
//   KM (k-major gmem rows feed it naturally when MN dim is contiguous):
//       tile[k][x ^ SWC(k)], row stride 136 — used for TA(A) / !TB(B)
//   XM (k contiguous in gmem): tile[x][k], row stride 20 — used for !TA / TB
// ---------------------------------------------------------------------------
template<bool TA, bool TB, bool RND>
__global__ __launch_bounds__(256)
void gemm_tc(const float* __restrict__ Ag, const float* __restrict__ Bg,
             float* __restrict__ Cg, int M, int N, int K,
             int lda, int ldb, int ldc,
             long as1, long as2, long bs1, long bs2, long cs1, long cs2)
{
    __shared__ __align__(16) float As[2][2560];
    __shared__ __align__(16) float Bs[2][2560];

    const int z = blockIdx.z;
    const float* A = Ag + (long)(z / HH) * as1 + (long)(z % HH) * as2;
    const float* B = Bg + (long)(z / HH) * bs1 + (long)(z % HH) * bs2;
    float* C = Cg + (long)(z / HH) * cs1 + (long)(z % HH) * cs2;

    const int m0 = blockIdx.y * 128;
    const int n0 = blockIdx.x * 128;
    const int tid = threadIdx.x;
    const int lane = tid & 31;
    const int wid = tid >> 5;              // 0..7
    const int wm = (wid & 1) * 64;         // 2 warps in M
    const int wn = (wid >> 1) * 32;        // 4 warps in N
    const int lm = lane >> 2;              // 0..7
    const int lk = lane & 3;               // 0..3

    float acc[4][4][4];
    #pragma unroll
    for (int i = 0; i < 4; i++)
        #pragma unroll
        for (int j = 0; j < 4; j++)
            #pragma unroll
            for (int r = 0; r < 4; r++) acc[i][j][r] = 0.f;

    // ---- stage loaders: 512 16B-chunks per operand tile, 2 per thread ----
    auto load_stage = [&](int buf, int kt) {
        #pragma unroll
        for (int i = 0; i < 2; i++) {
            const int c4 = tid + i * 256;
            // A tile
            if (!TA) {                       // XM: [m][k] stride 20
                const int m = c4 >> 2, kq = (c4 & 3) << 2;
                cpa16(sa(&As[buf][m * 20 + kq]),
                      &A[(long)(m0 + m) * lda + kt + kq], true);
            } else {                         // KM: [k][m^swz]
                const int k = c4 >> 5, m4 = (c4 & 31) << 2;
                cpa16(sa(&As[buf][k * 136 + (m4 ^ SWC(k))]),
                      &A[(long)(kt + k) * lda + m0 + m4], true);
            }
            // B tile
            if (TB) {                        // XM: [n][k] stride 20
                const int n = c4 >> 2, kq = (c4 & 3) << 2;
                const bool p = (n0 + n) < N;
                cpa16(sa(&Bs[buf][n * 20 + kq]),
                      &B[(long)(p ? n0 + n : 0) * ldb + kt + kq], p);
            } else {                         // KM: [k][n^swz]
                const int k = c4 >> 5, n4 = (c4 & 31) << 2;
                const bool p = (n0 + n4) < N;
                cpa16(sa(&Bs[buf][k * 136 + (n4 ^ SWC(k))]),
                      &B[(long)(kt + k) * ldb + (p ? n0 + n4 : 0)], p);
            }
        }
    };

    auto compute = [&](int buf) {
        const float* __restrict__ Ab = As[buf];
        const float* __restrict__ Bb = Bs[buf];
        #pragma unroll
        for (int ks = 0; ks < 2; ks++) {
            const int r1 = ks * 8 + lk;
            const int r2 = r1 + 4;
            unsigned a[4][4], b[4][2];
            if (!TA) {
                #pragma unroll
                for (int mt = 0; mt < 4; mt++) {
                    const int mr = wm + mt * 16 + lm;
                    a[mt][0] = __float_as_uint(Ab[mr * 20 + r1]);
                    a[mt][1] = __float_as_uint(Ab[(mr + 8) * 20 + r1]);
                    a[mt][2] = __float_as_uint(Ab[mr * 20 + r2]);
                    a[mt][3] = __float_as_uint(Ab[(mr + 8) * 20 + r2]);
                }
            } else {
                const int c1 = SWC(r1), c2 = SWC(r2);
                #pragma unroll
                for (int mt = 0; mt < 4; mt++) {
                    const int mr = wm + mt * 16 + lm;
                    a[mt][0] = __float_as_uint(Ab[r1 * 136 + (mr ^ c1)]);
                    a[mt][1] = __float_as_uint(Ab[r1 * 136 + ((mr + 8) ^ c1)]);
                    a[mt][2] = __float_as_uint(Ab[r2 * 136 + (mr ^ c2)]);
                    a[mt][3] = __float_as_uint(Ab[r2 * 136 + ((mr + 8) ^ c2)]);
                }
            }
            if (!TB) {
                const int c1 = SWC(r1), c2 = SWC(r2);
                #pragma unroll
                for (int nt = 0; nt < 4; nt++) {
                    const int nc = wn + nt * 8 + lm;
                    b[nt][0] = __float_as_uint(Bb[r1 * 136 + (nc ^ c1)]);
                    b[nt][1] = __float_as_uint(Bb[r2 * 136 + (nc ^ c2)]);
                }
            } else {
                #pragma unroll
                for (int nt = 0; nt < 4; nt++) {
                    const int nc = wn + nt * 8 + lm;
                    b[nt][0] = __float_as_uint(Bb[nc * 20 + r1]);
                    b[nt][1] = __float_as_uint(Bb[nc * 20 + r2]);
                }
            }
            #pragma unroll
            for (int mt = 0; mt < 4; mt++)
                #pragma unroll
                for (int nt = 0; nt < 4; nt++)
                    mma_tf32(acc[mt][nt], a[mt], b[nt]);
        }
    };

    // ---- 2-stage pipeline ----
    const int nk = K / 16;
    load_stage(0, 0);
    cp_commit();
    load_stage(1, 16);
    cp_commit();
    for (int t = 0; t < nk; t++) {
        cp_wait1();
        __syncthreads();
        compute(t & 1);
        __syncthreads();
        const int kt = (t + 2) * 16;
        if (kt < K) load_stage(t & 1, kt);
        cp_commit();
    }

    // ---- epilogue ----
    #pragma unroll
    for (int mt = 0; mt < 4; mt++) {
        const int r0 = m0 + wm + mt * 16 + lm;
        #pragma unroll
        for (int nt = 0; nt < 4; nt++) {
            const int c0 = n0 + wn + nt * 8 + 2 * lk;
            if (c0 < N) {
                float v0 = acc[mt][nt][0], v1 = acc[mt][nt][1];
                float v2 = acc[mt][nt][2], v3 = acc[mt][nt][3];
                if (RND) { v0 = rtf(v0); v1 = rtf(v1); v2 = rtf(v2); v3 = rtf(v3); }
                C[(long)r0 * ldc + c0]           = v0;
                C[(long)r0 * ldc + c0 + 1]       = v1;
                C[(long)(r0 + 8) * ldc + c0]     = v2;
                C[(long)(r0 + 8) * ldc + c0 + 1] = v3;
            }
        }
    }
}

// ---------------------------------------------------------------------------
// Elementwise tf32 pre-rounding (float4 granularity; n4 = n/4)
// ---------------------------------------------------------------------------
__global__ void round_kernel(const float* __restrict__ in, float* __restrict__ out, int n4)
{
    const int i = blockIdx.x * 256 + threadIdx.x;
    if (i < n4) {
        float4 v = ((const float4*)in)[i];
        v.x = rtf(v.x); v.y = rtf(v.y); v.z = rtf(v.z); v.w = rtf(v.w);
        ((float4*)out)[i] = v;
    }
}

// ---------------------------------------------------------------------------
// Row softmax (in place), output rounded to tf32 (it feeds GEMM 6).
// ---------------------------------------------------------------------------
__global__ void softmax_kernel(float* __restrict__ S, int cols)
{
    float* p = S + (long)blockIdx.x * cols;
    const int tid = threadIdx.x;
    __shared__ float red[8];

    float vmax = -1e30f;
    for (int i = tid; i < cols; i += 256) vmax = fmaxf(vmax, p[i]);
    #pragma unroll
    for (int o = 16; o > 0; o >>= 1) vmax = fmaxf(vmax, __shfl_xor_sync(~0u, vmax, o));
    if ((tid & 31) == 0) red[tid >> 5] = vmax;
    __syncthreads();
    if (tid < 32) {
        float v = (tid < 8) ? red[tid] : -1e30f;
        #pragma unroll
        for (int o = 4; o > 0; o >>= 1) v = fmaxf(v, __shfl_xor_sync(~0u, v, o));
        if (tid == 0) red[0] = v;
    }
    __syncthreads();
    vmax = red[0];
    __syncthreads();

    float s = 0.f;
    for (int i = tid; i < cols; i += 256) {
        const float e = __expf(p[i] - vmax);
        p[i] = e;
        s += e;
    }
    #pragma unroll
    for (int o = 16; o > 0; o >>= 1) s += __shfl_xor_sync(~0u, s, o);
    if ((tid & 31) == 0) red[tid >> 5] = s;
    __syncthreads();
    if (tid < 32) {
        float v = (tid < 8) ? red[tid] : 0.f;
        #pragma unroll
        for (int o = 4; o > 0; o >>= 1) v += __shfl_xor_sync(~0u, v, o);
        if (tid == 0) red[0] = v;
    }
    __syncthreads();
    const float inv = 1.0f / red[0];
    for (int i = tid; i < cols; i += 256) p[i] = rtf(p[i] * inv);
}

// ---------------------------------------------------------------------------
extern "C" void kernel_launch(void* const* d_in, const int* in_sizes, int n_in,
                              void* d_out, int out_size)
{
    const float* x = (const float*)d_in[0];   // [B, L, D]
    const float* k = (const float*)d_in[1];   // [H, D, D]
    const float* q = (const float*)d_in[2];   // [H, D, D]
    const float* v = (const float*)d_in[3];   // [H, DH, D]
    float* out = (float*)d_out;               // [B, L, D]

    float *pM, *pA, *pS, *pV, *px, *pk, *pq, *pv;
    cudaGetSymbolAddress((void**)&pM, g_M);
    cudaGetSymbolAddress((void**)&pA, g_A);
    cudaGetSymbolAddress((void**)&pS, g_S);
    cudaGetSymbolAddress((void**)&pV, g_V);
    cudaGetSymbolAddress((void**)&px, g_x);
    cudaGetSymbolAddress((void**)&pk, g_k);
    cudaGetSymbolAddress((void**)&pq, g_q);
    cudaGetSymbolAddress((void**)&pv, g_v);

    const long LD  = (long)LL * DD;
    const long L2  = (long)LL * LL;
    const long DSQ = (long)DD * DD;
    const long LDH = (long)LL * DHH;

    // 0) pre-round inputs to tf32
    {
        const int nx = BB * LL * DD / 4, nk2 = HH * DD * DD / 4, nv = HH * DHH * DD / 4;
        round_kernel<<<(nx + 255) / 256, 256>>>(x, px, nx);
        round_kernel<<<(nk2 + 255) / 256, 256>>>(k, pk, nk2);
        round_kernel<<<(nk2 + 255) / 256, 256>>>(q, pq, nk2);
        round_kernel<<<(nv + 255) / 256, 256>>>(v, pv, nv);
    }

    dim3 blk(256);

    // 1) M_n = q_n^T * k_n : [D,D,D], batch 12          (TA, !TB)  -> round
    gemm_tc<true, false, true><<<dim3(DD/128, DD/128, HH), blk>>>(
        pq, pk, pM, DD, DD, DD, DD, DD, DD,
        0, DSQ,   0, DSQ,   0, DSQ);

    // 2) A_bn = X_b * M_n : [L,D]x[D,D], batch 48       (!TA,!TB)  -> round
    gemm_tc<false, false, true><<<dim3(DD/128, LL/128, BB*HH), blk>>>(
        px, pM, pA, LL, DD, DD, DD, DD, DD,
        LD, 0,    0, DSQ,   HH*LD, LD);

    // 3) S = A_bn * X_b^T : [L,D]x[D,L], batch 48       (!TA, TB)  (softmax rounds)
    gemm_tc<false, true, false><<<dim3(LL/128, LL/128, BB*HH), blk>>>(
        pA, px, pS, LL, LL, DD, DD, DD, LL,
        HH*LD, LD,   LD, 0,   HH*L2, L2);

    // 4) softmax over last dim of S (rounds output to tf32)
    softmax_kernel<<<dim3(BB*HH*LL), dim3(256)>>>(pS, LL);

    // 5) Vt = X_b * v_n^T : [L,D]x[D,DH], batch 48      (!TA, TB)  -> round
    gemm_tc<false, true, true><<<dim3(1, LL/128, BB*HH), blk>>>(
        px, pv, pV, LL, DHH, DD, DD, DD, DHH,
        LD, 0,    0, (long)DHH*DD,   HH*LDH, LDH);

    // 6) out = S * Vt : [L,L]x[L,DH], batch 48          (!TA,!TB)  final, no round
    gemm_tc<false, false, false><<<dim3(1, LL/128, BB*HH), blk>>>(
        pS, pV, out, LL, DHH, LL, LL, DHH, DD,
        HH*L2, L2,   HH*LDH, LDH,   LD, DHH);
}